// round 16
// baseline (speedup 1.0000x reference)
#include <cuda_runtime.h>
#include <cuda_fp16.h>
#include <math.h>
#include <stdint.h>

#define HID     256
#define NT      31
#define NTREES  4096
#define NNODES  (NTREES*NT)       // 126976
#define NE_TREE 30
#define NE_HALF (NTREES*NE_TREE)  // 122880
#define VOCAB   780

// ---------------- scratch (static device globals; no allocation) ----------------
__device__ float g_s  [NNODES*HID];     // BU states
__device__ float g_rm [NNODES*HID];
__device__ float g_s2 [NNODES*HID];     // TD states (private -> BU/TD overlap)
__device__ float g_rm2[NNODES*HID];
__device__ float g_Pz[VOCAB*HID];
__device__ float g_Ph[VOCAB*HID];
__device__ float g_Pr[VOCAB*HID];
__device__ float g_Pf[VOCAB*HID];
__device__ float g_M0 [VOCAB*HID];
__device__ float g_MU0[VOCAB*HID];
__device__ __half g_W[8*HID*HID];     // transposed [n][k] fp16 (single-rounded)

__device__ __forceinline__ float sigf(float x){ return 1.0f/(1.0f+expf(-x)); }

__device__ __forceinline__ uint32_t smem_u32(const void* p){
    uint32_t a;
    asm("{ .reg .u64 t; cvta.to.shared.u64 t, %1; cvt.u32.u64 %0, t; }" : "=r"(a) : "l"(p));
    return a;
}
__device__ __forceinline__ void ldsm_x4(uint32_t a, uint32_t* r){
    asm volatile("ldmatrix.sync.aligned.m8n8.x4.shared.b16 {%0,%1,%2,%3}, [%4];"
        : "=r"(r[0]),"=r"(r[1]),"=r"(r[2]),"=r"(r[3]) : "r"(a));
}
__device__ __forceinline__ void mma_f16(float* d, const uint32_t* a, const uint32_t* b){
    asm volatile("mma.sync.aligned.m16n8k16.row.col.f32.f16.f16.f32 "
        "{%0,%1,%2,%3}, {%4,%5,%6,%7}, {%8,%9}, {%0,%1,%2,%3};"
        : "+f"(d[0]),"+f"(d[1]),"+f"(d[2]),"+f"(d[3])
        : "r"(a[0]),"r"(a[1]),"r"(a[2]),"r"(a[3]), "r"(b[0]),"r"(b[1]));
}
__device__ __forceinline__ void cp16(uint32_t dst, const void* src){
    asm volatile("cp.async.cg.shared.global [%0], [%1], 16;" :: "r"(dst), "l"(src));
}
#define CP_COMMIT() asm volatile("cp.async.commit_group;" ::: "memory")
#define CP_WAIT0()  asm volatile("cp.async.wait_group 0;" ::: "memory")
#define CP_WAIT1()  asm volatile("cp.async.wait_group 1;" ::: "memory")
#define SWZ(o) ((o) ^ (((o) >> 3) & 0x70))

// ==================================================================
// LEVEL MEGA-KERNEL: per CTA, 64 rows x all 256 cols, one tree level.
// Phase 0: stage A1=s, A2=rm rows (fp16, 8 chunks x 4KB each).
// Phase 1: flat 32 iters (cc 0..3, kc 0..7): accZ += A1@Wzs, accH += A2@Whs;
//          at kc==7: z=sig(+Pz), h=tanh(+Ph), m=(1-z)s+z*h -> out (fp32)
//          + m -> smem fp16 (R-GEMM operand).
// Phase 2: flat 32 iters: acc += m@Ur; at kc==7: BU: r=sig(+Pr[parent]),
//          pair-reduce m,m*r -> g_s/g_rm; TD: children -> g_s2/g_rm2.
// SMEM: A1[0,32K) A2[32K,64K) M[64K,96K) Wstages[96K,112K) (2 x 8K)
// ==================================================================
#define A1_OFF 0
#define A2_OFF 32768
#define M_OFF  65536
#define W_OFF  98304
#define LV_SMEM 114688

__global__ void __launch_bounds__(128,2) level_k(
    const float* __restrict__ S1, const float* __restrict__ S2,
    const int* __restrict__ wid, float* __restrict__ out,
    int aL, int aBase, int td)
{
    extern __shared__ char sm[];
    const uint32_t sb = smem_u32(sm);
    const int tid = threadIdx.x, l = tid & 31, w = tid >> 5;
    const int row0 = blockIdx.x * 64;
    const int mask = (1 << aL) - 1;

    // ---- A loader mapping (2 thr/row) ----
    const int arow = tid >> 1, ahalf = tid & 1;
    {
    }
    const int argl = row0 + arow;
    const int ltree = argl >> aL, ljj = argl & mask;
    const int lnode = ltree * NT + aBase + ljj;
    const float* A1row = S1 + (size_t)lnode * HID;
    const float* A2row = S2 + (size_t)lnode * HID;
    const uint32_t abase = (uint32_t)((arow >> 1)*128 + (arow & 1)*64 + ahalf*32);

    // ---- epilogue row metadata ----
    int rgs[2]; rgs[0] = row0 + w*16 + (l>>2); rgs[1] = rgs[0] + 8;
    int ndA[2], widA[2], widB0[2], widB1[2], par[2], chl[2];
    size_t eOut[2];
    #pragma unroll
    for (int i = 0; i < 2; i++) {
        int rg = rgs[i], tr = rg >> aL, q = rg & mask;
        if (!td) {
            int child = tr*NT + aBase + q;
            ndA[i]  = child;  widA[i] = wid[child];
            par[i]  = tr*NT + ((aBase + q - 1) >> 1);
            widB0[i] = wid[par[i]]; widB1[i] = 0; chl[i] = 0;
            eOut[i] = (size_t)(tr*NE_TREE + aBase - 1 + q) * HID;
        } else {
            int pl = aBase + q;
            int parent = tr*NT + pl;
            ndA[i]  = parent; widA[i] = wid[parent];
            chl[i]  = tr*NT + 2*pl + 1;
            widB0[i] = wid[chl[i]]; widB1[i] = wid[chl[i]+1]; par[i] = 0;
            eOut[i] = ((size_t)NE_HALF + (size_t)tr*NE_TREE + 2*pl) * HID;
        }
    }

#define ISSUE_W1(st, it) do { \
    int cc_ = (it) >> 3, kc_ = (it) & 7; \
    uint32_t dst = sb + W_OFF + (uint32_t)(st)*8192u; \
    _Pragma("unroll") \
    for (int e = 0; e < 2; e++) { \
        int idx = tid*2 + e; int wnr = idx >> 2, wu = idx & 3; \
        uint32_t wo = SWZ((uint32_t)((wnr>>1)*128 + (wnr&1)*64 + wu*16)); \
        size_t so = (size_t)(cc_*64 + wnr)*HID + kc_*32 + wu*8; \
        cp16(dst + wo,          g_W + (size_t)1*65536 + so); \
        cp16(dst + 4096u + wo,  g_W + (size_t)3*65536 + so); \
    } \
} while(0)
#define ISSUE_W2(st, it) do { \
    int cc_ = (it) >> 3, kc_ = (it) & 7; \
    uint32_t dst = sb + W_OFF + (uint32_t)(st)*8192u; \
    _Pragma("unroll") \
    for (int e = 0; e < 2; e++) { \
        int idx = tid*2 + e; int wnr = idx >> 2, wu = idx & 3; \
        uint32_t wo = SWZ((uint32_t)((wnr>>1)*128 + (wnr&1)*64 + wu*16)); \
        cp16(dst + wo, g_W + (size_t)5*65536 + (size_t)(cc_*64 + wnr)*HID + kc_*32 + wu*8); \
    } \
} while(0)
#define STAGE_A(dstOff, Arow) do { \
    _Pragma("unroll 1") \
    for (int c = 0; c < 8; c++) { \
        float4 v[4]; \
        _Pragma("unroll") \
        for (int i2 = 0; i2 < 4; i2++) \
            v[i2] = *(const float4*)((Arow) + c*32 + ahalf*16 + i2*4); \
        uint32_t pk[8]; \
        _Pragma("unroll") \
        for (int i2 = 0; i2 < 4; i2++) { \
            __half2 q0 = __floats2half2_rn(v[i2].x, v[i2].y); \
            __half2 q1 = __floats2half2_rn(v[i2].z, v[i2].w); \
            pk[2*i2] = *(uint32_t*)&q0; pk[2*i2+1] = *(uint32_t*)&q1; \
        } \
        char* bp = sm + (dstOff) + c*4096; \
        *(uint4*)(bp + SWZ(abase))      = make_uint4(pk[0],pk[1],pk[2],pk[3]); \
        *(uint4*)(bp + SWZ(abase+16))   = make_uint4(pk[4],pk[5],pk[6],pk[7]); \
    } \
} while(0)

    // ---- phase 0 ----
    ISSUE_W1(0, 0); CP_COMMIT();
    STAGE_A(A1_OFF, A1row);
    STAGE_A(A2_OFF, A2row);

    float accZ[8][4], accH[8][4];
    const int mi = l >> 3;

    // ---- phase 1: Z and H GEMMs + m elementwise ----
    #pragma unroll 1
    for (int it = 0; it < 32; it++) {
        const int st = it & 1, cc = it >> 3, kc = it & 7;
        if (kc == 0) {
            #pragma unroll
            for (int a = 0; a < 8; a++)
                #pragma unroll
                for (int q = 0; q < 4; q++) { accZ[a][q] = 0.f; accH[a][q] = 0.f; }
        }
        CP_WAIT0();
        __syncthreads();
        if (it < 31) { ISSUE_W1(st ^ 1, it + 1); CP_COMMIT(); }

        const uint32_t wb = sb + W_OFF + (uint32_t)st*8192u;
        #pragma unroll
        for (int ks = 0; ks < 2; ks++) {
            uint32_t a1[4], a2[4];
            {
                int rrow = w*16 + (l & 15);
                int kb = ks*16 + (l >> 4)*8;
                uint32_t ao = SWZ((uint32_t)((rrow>>1)*128 + (rrow&1)*64 + kb*2));
                ldsm_x4(sb + A1_OFF + kc*4096 + ao, a1);
                ldsm_x4(sb + A2_OFF + kc*4096 + ao, a2);
            }
            #pragma unroll
            for (int p = 0; p < 4; p++) {
                int nrow = p*16 + (mi>>1)*8 + (l&7);
                int kb2 = ks*16 + (mi&1)*8;
                uint32_t wo = SWZ((uint32_t)((nrow>>1)*128 + (nrow&1)*64 + kb2*2));
                uint32_t wz[4], wh[4];
                ldsm_x4(wb + wo, wz);
                ldsm_x4(wb + 4096u + wo, wh);
                mma_f16(accZ[2*p],   a1, &wz[0]);
                mma_f16(accZ[2*p+1], a1, &wz[2]);
                mma_f16(accH[2*p],   a2, &wh[0]);
                mma_f16(accH[2*p+1], a2, &wh[2]);
            }
        }
        if (kc == 7) {
            #pragma unroll
            for (int i = 0; i < 2; i++) {
                const float* pz = g_Pz + (size_t)widA[i]*HID;
                const float* ph = g_Ph + (size_t)widA[i]*HID;
                const float* sr = S1 + (size_t)ndA[i]*HID;
                float* o0 = out + eOut[i];
                int rloc = w*16 + (l>>2) + 8*i;
                #pragma unroll
                for (int ns = 0; ns < 8; ns++) {
                    int c = cc*64 + ns*8 + (l&3)*2;
                    float m0, m1;
                    {
                        float z = sigf (accZ[ns][i*2+0] + pz[c]);
                        float h = tanhf(accH[ns][i*2+0] + ph[c]);
                        m0 = (1.f - z) * sr[c] + z * h;
                    }
                    {
                        float z = sigf (accZ[ns][i*2+1] + pz[c+1]);
                        float h = tanhf(accH[ns][i*2+1] + ph[c+1]);
                        m1 = (1.f - z) * sr[c+1] + z * h;
                    }
                    *(float2*)(o0 + c) = make_float2(m0, m1);
                    if (td) *(float2*)(o0 + HID + c) = make_float2(m0, m1);
                    __half2 mh = __floats2half2_rn(m0, m1);
                    int chunk = c >> 5, kk = c & 31;
                    *(uint32_t*)(sm + M_OFF + chunk*4096 +
                        SWZ((uint32_t)((rloc>>1)*128 + (rloc&1)*64 + kk*2))) = *(uint32_t*)&mh;
                }
            }
        }
    }

    // ---- phase 2: R = m @ Ur + fused epilogue ----
    ISSUE_W2(0, 0); CP_COMMIT();
    #pragma unroll 1
    for (int it = 0; it < 32; it++) {
        const int st = it & 1, cc = it >> 3, kc = it & 7;
        if (kc == 0) {
            #pragma unroll
            for (int a = 0; a < 8; a++)
                #pragma unroll
                for (int q = 0; q < 4; q++) accZ[a][q] = 0.f;
        }
        CP_WAIT0();
        __syncthreads();
        if (it < 31) { ISSUE_W2(st ^ 1, it + 1); CP_COMMIT(); }

        const uint32_t wb = sb + W_OFF + (uint32_t)st*8192u;
        #pragma unroll
        for (int ks = 0; ks < 2; ks++) {
            uint32_t am[4];
            {
                int rrow = w*16 + (l & 15);
                int kb = ks*16 + (l >> 4)*8;
                ldsm_x4(sb + M_OFF + kc*4096 +
                        SWZ((uint32_t)((rrow>>1)*128 + (rrow&1)*64 + kb*2)), am);
            }
            #pragma unroll
            for (int p = 0; p < 4; p++) {
                int nrow = p*16 + (mi>>1)*8 + (l&7);
                int kb2 = ks*16 + (mi&1)*8;
                uint32_t wu4[4];
                ldsm_x4(wb + SWZ((uint32_t)((nrow>>1)*128 + (nrow&1)*64 + kb2*2)), wu4);
                mma_f16(accZ[2*p],   am, &wu4[0]);
                mma_f16(accZ[2*p+1], am, &wu4[2]);
            }
        }
        if (kc == 7) {
            #pragma unroll
            for (int i = 0; i < 2; i++) {
                const float* mrow = out + eOut[i];
                if (!td) {
                    const float* pr = g_Pr + (size_t)widB0[i]*HID;
                    float* ds = g_s  + (size_t)par[i]*HID;
                    float* dr = g_rm + (size_t)par[i]*HID;
                    #pragma unroll
                    for (int ns = 0; ns < 8; ns++) {
                        int c = cc*64 + ns*8 + (l&3)*2;
                        #pragma unroll
                        for (int u = 0; u < 2; u++) {
                            float r = sigf(accZ[ns][i*2+u] + pr[c+u]);
                            float m = mrow[c+u];
                            float mr = m * r;
                            float msum  = m  + __shfl_xor_sync(0xffffffffu, m, 4);
                            float mrsum = mr + __shfl_xor_sync(0xffffffffu, mr, 4);
                            if (!(l & 4)) { ds[c+u] = msum; dr[c+u] = mrsum; }
                        }
                    }
                } else {
                    const float* p0 = g_Pr + (size_t)widB0[i]*HID;
                    const float* p1 = g_Pr + (size_t)widB1[i]*HID;
                    float* s0 = g_s2  + (size_t)chl[i]*HID;
                    float* r0 = g_rm2 + (size_t)chl[i]*HID;
                    #pragma unroll
                    for (int ns = 0; ns < 8; ns++) {
                        int c = cc*64 + ns*8 + (l&3)*2;
                        #pragma unroll
                        for (int u = 0; u < 2; u++) {
                            float a = accZ[ns][i*2+u];
                            float m = mrow[c+u];
                            s0[c+u]       = m;
                            s0[HID + c+u] = m;
                            r0[c+u]       = m * sigf(a + p0[c+u]);
                            r0[HID + c+u] = m * sigf(a + p1[c+u]);
                        }
                    }
                }
            }
        }
    }
#undef ISSUE_W1
#undef ISSUE_W2
#undef STAGE_A
}

// ==================================================================
// Small GEMM (round-15 proven): used for vocab tables, MU0, h_root.
// modes: 0 C=acc(+bias) [bounds]; 6 C=relu(acc+P[wid[node]]) [bounds]
// ==================================================================
struct GJob {
    const float* A;
    float*       C;
    const float* P;
    const float* bias;
    int mat;
    int mode;
};

#define STAGE_B 8192
#define SM_SNG  (3*STAGE_B)

__global__ void __launch_bounds__(128,4) gemm_s(
    GJob j0, GJob j1, GJob j2, GJob j3,
    int aL, int aRS, int aBase, int R,
    const int* __restrict__ wid)
{
    extern __shared__ char sm[];
    const uint32_t sb = smem_u32(sm);
    const int tid = threadIdx.x, l = tid & 31, w = tid >> 5;
    const int row0 = blockIdx.x * 64, col0 = blockIdx.y * 64;
    const int aMask = (1 << aL) - 1;

    const GJob j = (blockIdx.z == 0) ? j0 : (blockIdx.z == 1) ? j1
                 : (blockIdx.z == 2) ? j2 : j3;
    const int mode = j.mode;

    const int arow = tid >> 1, ahalf = tid & 1;
    const int argl = row0 + arow;
    const float* Asrc = nullptr;
    if (argl < R) {
        int an = ((argl >> aL) * aRS) + aBase + (argl & aMask);
        Asrc = j.A + (size_t)an * HID;
    }
    const uint32_t abase = (uint32_t)((arow >> 1)*128 + (arow & 1)*64 + ahalf*32);

    uint32_t wdo[2];
    const __half* wsrc[2];
    #pragma unroll
    for (int e = 0; e < 2; e++) {
        int idx = tid*2 + e;
        int wnr = idx >> 2, wu = idx & 3;
        wsrc[e] = g_W + (size_t)j.mat * HID * HID + (size_t)(col0 + wnr) * HID + wu * 8;
        wdo[e] = 4096u + SWZ((uint32_t)((wnr >> 1)*128 + (wnr & 1)*64 + wu*16));
    }

    int rgs[2];
    rgs[0] = row0 + w*16 + (l >> 2);
    rgs[1] = rgs[0] + 8;
    int pwa[2] = {0, 0};
    #pragma unroll
    for (int i = 0; i < 2; i++) {
        int rg = rgs[i];
        if (mode == 6 && rg < R) {
            int nd = ((rg >> aL) * aRS) + aBase + (rg & aMask);
            pwa[i] = wid[nd];
        }
    }

    float acc[8][4];
    #pragma unroll
    for (int a = 0; a < 8; a++)
        #pragma unroll
        for (int q = 0; q < 4; q++) acc[a][q] = 0.f;

    float4 av[4];
#define LDA(kc) do { \
    _Pragma("unroll") \
    for (int i2 = 0; i2 < 4; i2++) \
        av[i2] = Asrc ? *(const float4*)(Asrc + (kc)*32 + ahalf*16 + i2*4) \
                      : make_float4(0.f,0.f,0.f,0.f); \
} while(0)
#define STSA(st) do { \
    char* bp = sm + (st)*STAGE_B; \
    uint32_t pk[8]; \
    _Pragma("unroll") \
    for (int i2 = 0; i2 < 4; i2++) { \
        __half2 q0 = __floats2half2_rn(av[i2].x, av[i2].y); \
        __half2 q1 = __floats2half2_rn(av[i2].z, av[i2].w); \
        pk[2*i2]   = *(uint32_t*)&q0; \
        pk[2*i2+1] = *(uint32_t*)&q1; \
    } \
    *(uint4*)(bp + SWZ(abase))      = make_uint4(pk[0], pk[1], pk[2], pk[3]); \
    *(uint4*)(bp + SWZ(abase + 16)) = make_uint4(pk[4], pk[5], pk[6], pk[7]); \
} while(0)
#define CPW(st, kc) do { \
    uint32_t bb = sb + (st)*STAGE_B; \
    cp16(bb + wdo[0], wsrc[0] + (kc)*32); \
    cp16(bb + wdo[1], wsrc[1] + (kc)*32); \
} while(0)

    LDA(0);
    CPW(0, 0); CP_COMMIT();
    CPW(1, 1); CP_COMMIT();
    STSA(0);
    LDA(1);

    const int mi = l >> 3;
    #pragma unroll 1
    for (int kc = 0; kc < 8; kc++) {
        if (kc < 7) CP_WAIT1(); else CP_WAIT0();
        __syncthreads();
        int stn = kc + 2; stn -= (stn >= 3) ? 3 : 0; stn -= (stn >= 3) ? 3 : 0;
        if (kc < 6) { CPW(stn, kc + 2); }
        CP_COMMIT();

        int st = kc; st -= (st >= 3) ? 3 : 0; st -= (st >= 3) ? 3 : 0;
        const uint32_t sA = sb + st * STAGE_B;
        #pragma unroll
        for (int ks = 0; ks < 2; ks++) {
            uint32_t fa[4];
            {
                int rrow = w*16 + (l & 15);
                int kb = ks*16 + (l >> 4)*8;
                ldsm_x4(sA + SWZ((uint32_t)((rrow>>1)*128 + (rrow&1)*64 + kb*2)), fa);
            }
            #pragma unroll
            for (int p = 0; p < 4; p++) {
                int nrow = p*16 + (mi>>1)*8 + (l&7);
                int kb2 = ks*16 + (mi&1)*8;
                uint32_t bw[4];
                ldsm_x4(sA + 4096 + SWZ((uint32_t)((nrow>>1)*128 + (nrow&1)*64 + kb2*2)), bw);
                mma_f16(acc[2*p],   fa, &bw[0]);
                mma_f16(acc[2*p+1], fa, &bw[2]);
            }
        }
        if (kc < 7) {
            int sts = kc + 1; sts -= (sts >= 3) ? 3 : 0; sts -= (sts >= 3) ? 3 : 0;
            STSA(sts);
            if (kc < 6) LDA(kc + 2);
        }
    }
#undef LDA
#undef STSA
#undef CPW

    #pragma unroll
    for (int i = 0; i < 2; i++) {
        int rg = rgs[i];
        if (rg >= R) continue;
        float* crow = j.C + (size_t)rg * HID;
        if (mode == 0) {
            #pragma unroll
            for (int ns = 0; ns < 8; ns++) {
                int c = col0 + ns*8 + (l&3)*2;
                float v0 = acc[ns][i*2+0], v1 = acc[ns][i*2+1];
                if (j.bias) { v0 += j.bias[c]; v1 += j.bias[c+1]; }
                *(float2*)(crow + c) = make_float2(v0, v1);
            }
        } else {
            const float* prow = j.P + (size_t)pwa[i] * HID;
            #pragma unroll
            for (int ns = 0; ns < 8; ns++) {
                int c = col0 + ns*8 + (l&3)*2;
                float v0 = fmaxf(acc[ns][i*2+0] + prow[c],   0.f);
                float v1 = fmaxf(acc[ns][i*2+1] + prow[c+1], 0.f);
                *(float2*)(crow + c) = make_float2(v0, v1);
            }
        }
    }
}

// ---------------- weight transpose + fp16 prep ----------------
__global__ void k_prepw(const float* __restrict__ Wz, const float* __restrict__ Wh,
                        const float* __restrict__ Wr, const float* __restrict__ Ur,
                        const float* __restrict__ Wf)
{
    const float* src;
    switch (blockIdx.x) {
        case 0: src = Wz; break;            case 1: src = Wz + 256*HID; break;
        case 2: src = Wh; break;            case 3: src = Wh + 256*HID; break;
        case 4: src = Wr; break;            case 5: src = Ur; break;
        case 6: src = Wf; break;            default: src = Wf + 256*HID; break;
    }
    int n = threadIdx.x;
    size_t mb = (size_t)blockIdx.x * HID * HID;
    int k0 = blockIdx.y * 32;
    for (int k = k0; k < k0 + 32; k++) {
        g_W[mb + (size_t)n * HID + k] = __float2half_rn(src[(size_t)k * HID + n]);
    }
}

// ---------------- structural / elementwise kernels ----------------
__global__ void k_M0() {
    size_t o = (size_t)blockIdx.x * HID + threadIdx.x;
    g_M0[o] = sigf(g_Pz[o]) * tanhf(g_Ph[o]);
}

__global__ void k_bu_leaf(const int* __restrict__ wid, float* __restrict__ out) {
    int p = blockIdx.x, jl = threadIdx.x;
    int tree = p >> 3, q = p & 7;
    int pl = 7 + q;
    int parent = tree * NT + pl;
    int c0 = 2 * pl + 1;
    int child0 = tree * NT + c0;
    int w0 = wid[child0], w1 = wid[child0 + 1];
    float pr = g_Pr[(size_t)wid[parent] * HID + jl];
    float m0 = g_M0[(size_t)w0 * HID + jl];
    float m1 = g_M0[(size_t)w1 * HID + jl];
    float r0 = sigf(pr + g_MU0[(size_t)w0 * HID + jl]);
    float r1 = sigf(pr + g_MU0[(size_t)w1 * HID + jl]);
    size_t e0 = (size_t)(tree * NE_TREE + c0 - 1) * HID + jl;
    out[e0]       = m0;
    out[e0 + HID] = m1;
    size_t po = (size_t)parent * HID + jl;
    g_s[po]  = m0 + m1;
    g_rm[po] = m0 * r0 + m1 * r1;
}

__global__ void k_td_root(const int* __restrict__ wid, float* __restrict__ out) {
    int tree = blockIdx.x, jl = threadIdx.x;
    int wr = wid[tree * NT];
    float m  = g_M0 [(size_t)wr * HID + jl];
    float mu = g_MU0[(size_t)wr * HID + jl];
    #pragma unroll
    for (int c = 1; c <= 2; c++) {
        int child = tree * NT + c;
        float r = sigf(g_Pr[(size_t)wid[child] * HID + jl] + mu);
        size_t co = (size_t)child * HID + jl;
        g_s2[co]  = m;
        g_rm2[co] = m * r;
        out[(size_t)(NE_HALF + tree * NE_TREE + c - 1) * HID + jl] = m;
    }
}

// ---------------- host ----------------
static inline void launch_g(const GJob* js, int nz,
                            int aL, int aRS, int aBase, int R, const int* wid,
                            cudaStream_t st)
{
    dim3 g((R + 63) / 64, 4, nz);
    gemm_s<<<g, 128, SM_SNG, st>>>(
        js[0], (nz>1)?js[1]:js[0], (nz>2)?js[2]:js[0], (nz>3)?js[3]:js[0],
        aL, aRS, aBase, R, wid);
}

extern "C" void kernel_launch(void* const* d_in, const int* in_sizes, int n_in,
                              void* d_out, int out_size)
{
    const int*   wid = (const int*)  d_in[0];
    const float* emb = (const float*)d_in[1];
    const float* Wz  = (const float*)d_in[2];
    const float* bz  = (const float*)d_in[3];
    const float* Wh  = (const float*)d_in[4];
    const float* bh  = (const float*)d_in[5];
    const float* Wr  = (const float*)d_in[6];
    const float* Ur  = (const float*)d_in[7];
    const float* bu  = (const float*)d_in[8];
    const float* Wf  = (const float*)d_in[9];
    const float* bf  = (const float*)d_in[10];
    float* out = (float*)d_out;

    float *p_s, *p_rm, *p_s2, *p_rm2, *p_Pz, *p_Ph, *p_Pr, *p_Pf, *p_M0, *p_MU0;
    cudaGetSymbolAddress((void**)&p_s,   g_s);
    cudaGetSymbolAddress((void**)&p_rm,  g_rm);
    cudaGetSymbolAddress((void**)&p_s2,  g_s2);
    cudaGetSymbolAddress((void**)&p_rm2, g_rm2);
    cudaGetSymbolAddress((void**)&p_Pz,  g_Pz);
    cudaGetSymbolAddress((void**)&p_Ph,  g_Ph);
    cudaGetSymbolAddress((void**)&p_Pr,  g_Pr);
    cudaGetSymbolAddress((void**)&p_Pf,  g_Pf);
    cudaGetSymbolAddress((void**)&p_M0,  g_M0);
    cudaGetSymbolAddress((void**)&p_MU0, g_MU0);

    cudaFuncSetAttribute(gemm_s,  cudaFuncAttributeMaxDynamicSharedMemorySize, SM_SNG);
    cudaFuncSetAttribute(level_k, cudaFuncAttributeMaxDynamicSharedMemorySize, LV_SMEM);

    static cudaStream_t s_td = nullptr;
    static cudaEvent_t  ev_f = nullptr, ev_j = nullptr;
    if (!s_td) {
        cudaStreamCreateWithFlags(&s_td, cudaStreamNonBlocking);
        cudaEventCreateWithFlags(&ev_f, cudaEventDisableTiming);
        cudaEventCreateWithFlags(&ev_j, cudaEventDisableTiming);
    }

    // ---- prep: weights + vocab tables ----
    k_prepw<<<dim3(8, 8), 256>>>(Wz, Wh, Wr, Ur, Wf);
    {
        GJob js[4] = {
            { emb, p_Pz, nullptr, bz, 0, 0 },
            { emb, p_Ph, nullptr, bh, 2, 0 },
            { emb, p_Pr, nullptr, bu, 4, 0 },
            { emb, p_Pf, nullptr, bf, 6, 0 },
        };
        launch_g(js, 4, 0, 1, 0, VOCAB, wid, 0);
    }
    k_M0<<<VOCAB, HID>>>();
    {
        GJob js[1] = { { p_M0, p_MU0, nullptr, nullptr, 5, 0 } };
        launch_g(js, 1, 0, 1, 0, VOCAB, wid, 0);
    }

    // ---- fork TD onto s_td ----
    cudaEventRecord(ev_f, 0);
    cudaStreamWaitEvent(s_td, ev_f, 0);

    // ===== bottom-up (stream 0) =====
    k_bu_leaf<<<NTREES * 8, HID>>>(wid, out);
    for (int d = 2; d >= 0; d--) {
        int L = d + 1;
        int base = (1 << (d + 1)) - 1;
        int E = NTREES << (d + 1);
        level_k<<<E / 64, 128, LV_SMEM>>>(p_s, p_rm, wid, out, L, base, 0);
    }
    {   // h_root = relu(Pf[wid_root] + s_root @ Wfs)
        GJob jf[1] = { { p_s, out + (size_t)2 * NE_HALF * HID, p_Pf, nullptr, 7, 6 } };
        launch_g(jf, 1, 0, NT, 0, NTREES, wid, 0);
    }

    // ===== top-down (s_td) =====
    k_td_root<<<NTREES, HID, 0, s_td>>>(wid, out);
    for (int d = 1; d <= 3; d++) {
        int pb = (1 << d) - 1;
        int Pn = NTREES << d;
        level_k<<<Pn / 64, 128, LV_SMEM, s_td>>>(p_s2, p_rm2, wid, out, d, pb, 1);
    }

    // ---- join ----
    cudaEventRecord(ev_j, s_td);
    cudaStreamWaitEvent(0, ev_j, 0);
}

// round 17
// speedup vs baseline: 1.3206x; 1.3206x over previous
#include <cuda_runtime.h>
#include <cuda_fp16.h>
#include <math.h>
#include <stdint.h>

#define HID     256
#define NT      31
#define NTREES  4096
#define NNODES  (NTREES*NT)       // 126976
#define NE_TREE 30
#define NE_HALF (NTREES*NE_TREE)  // 122880
#define VOCAB   780

// ---------------- scratch (static device globals; no allocation) ----------------
__device__ float g_s  [NNODES*HID];     // BU states
__device__ float g_rm [NNODES*HID];
__device__ float g_s2 [NNODES*HID];     // TD states (private -> BU/TD overlap)
__device__ float g_rm2[NNODES*HID];
__device__ float g_T1 [32768*HID];      // BU z
__device__ float g_T2 [32768*HID];      // BU h(tanh)
__device__ float g_T1b[32768*HID];      // TD z
__device__ float g_T2b[32768*HID];      // TD h(tanh)
__device__ float g_Pz[VOCAB*HID];
__device__ float g_Ph[VOCAB*HID];
__device__ float g_Pr[VOCAB*HID];
__device__ float g_Pf[VOCAB*HID];
__device__ float g_M0 [VOCAB*HID];
__device__ float g_MU0[VOCAB*HID];
__device__ __half g_W[8*HID*HID];     // transposed [n][k] fp16 (single-rounded)

__device__ __forceinline__ float sigf(float x){ return 1.0f/(1.0f+expf(-x)); }

__device__ __forceinline__ uint32_t smem_u32(const void* p){
    uint32_t a;
    asm("{ .reg .u64 t; cvta.to.shared.u64 t, %1; cvt.u32.u64 %0, t; }" : "=r"(a) : "l"(p));
    return a;
}
__device__ __forceinline__ void ldsm_x4(uint32_t a, uint32_t* r){
    asm volatile("ldmatrix.sync.aligned.m8n8.x4.shared.b16 {%0,%1,%2,%3}, [%4];"
        : "=r"(r[0]),"=r"(r[1]),"=r"(r[2]),"=r"(r[3]) : "r"(a));
}
__device__ __forceinline__ void mma_f16(float* d, const uint32_t* a, const uint32_t* b){
    asm volatile("mma.sync.aligned.m16n8k16.row.col.f32.f16.f16.f32 "
        "{%0,%1,%2,%3}, {%4,%5,%6,%7}, {%8,%9}, {%0,%1,%2,%3};"
        : "+f"(d[0]),"+f"(d[1]),"+f"(d[2]),"+f"(d[3])
        : "r"(a[0]),"r"(a[1]),"r"(a[2]),"r"(a[3]), "r"(b[0]),"r"(b[1]));
}
__device__ __forceinline__ void cp16(uint32_t dst, const void* src){
    asm volatile("cp.async.cg.shared.global [%0], [%1], 16;" :: "r"(dst), "l"(src));
}
#define CP_COMMIT() asm volatile("cp.async.commit_group;" ::: "memory")
#define CP_WAIT0()  asm volatile("cp.async.wait_group 0;" ::: "memory")
#define CP_WAIT1()  asm volatile("cp.async.wait_group 1;" ::: "memory")
#define SWZ(o) ((o) ^ (((o) >> 3) & 0x70))

// ==================================================================
// Pipelined single-fp16 GEMM, tile 64x128, 256 thr (8 warps: 4M x 2N),
// grid (R/64, 2, nz). K-chunk 32, 3 stages x 12KB:
//   A fp16 [0,4K) packed 2 rows/128B; W fp16 [4K,12K) 128 n-rows packed.
// acc += A@W  (single MMA per product).
// node(rg) = (rg>>aL)*aRS + aBase + (rg & ((1<<aL)-1))
// modes: 0 C=acc(+bias) [bounds]; 1 C=sig(acc+P[wid[node]]);
//        2 C=tanh(acc+P[wid[node]]); 6 C=relu(acc+P[wid[node]]) [bounds]
//   Fused-m modes (Az/Ah set; loader computes m=(1-z)s+z*h, y==0 writes out):
//        3 BU-R: A=m; r=sig(acc+P[wid[parent]]); pair-reduce -> g_s/g_rm
//        5 TD-R: A=m; children r -> g_s2/g_rm2; out rows 2x per parent
// ==================================================================
struct GJob {
    const float* A;     // state source (plain A, or s for fused m)
    const float* Az;    // z rows (fused) or null
    const float* Ah;    // h rows (fused) or null
    float*       C;
    const float* P;
    const float* bias;
    float*       O;     // d_out base (fused modes)
    int mat;
    int mode;
};

#define STAGE_B 12288
#define SM_TOT  (3*STAGE_B)

__global__ void __launch_bounds__(256,2) gemm_s(
    GJob j0, GJob j1, GJob j2, GJob j3,
    int aL, int aRS, int aBase, int R,
    const int* __restrict__ wid, int dlev, int base)
{
    extern __shared__ char sm[];
    const uint32_t sb = smem_u32(sm);
    const int tid = threadIdx.x, l = tid & 31, w = tid >> 5;
    const int wm = w & 3, wn = w >> 2;
    const int row0 = blockIdx.x * 64, col0 = blockIdx.y * 128;
    const int aMask = (1 << aL) - 1;

    const GJob j = (blockIdx.z == 0) ? j0 : (blockIdx.z == 1) ? j1
                 : (blockIdx.z == 2) ? j2 : j3;
    const int mode = j.mode;

    // ---- A loader: 4 thr/row (64 rows), 8 floats -> 8 halves per chunk ----
    const int arow = tid >> 2, aq = tid & 3;
    const int argl = row0 + arow;
    const float *Asrc = nullptr, *Azr = nullptr, *Ahr = nullptr;
    float *Om0 = nullptr, *Om1 = nullptr;
    if (argl < R) {
        int an = ((argl >> aL) * aRS) + aBase + (argl & aMask);
        Asrc = j.A + (size_t)an * HID;
        if (j.Az) {
            Azr = j.Az + (size_t)argl * HID;
            Ahr = j.Ah + (size_t)argl * HID;
            if (blockIdx.y == 0) {
                int tree = argl >> aL, q = argl & aMask;
                if (mode == 3) {
                    Om0 = j.O + (size_t)(tree * NE_TREE + base - 1 + q) * HID;
                } else {
                    int pl = aBase + q;
                    Om0 = j.O + ((size_t)NE_HALF + (size_t)tree * NE_TREE + 2 * pl) * HID;
                    Om1 = Om0 + HID;
                }
            }
        }
    }
    const uint32_t abase = (uint32_t)((arow >> 1) * 128 + (arow & 1) * 64 + aq * 16);

    // ---- W loader: 2 cp16/thr/chunk (128 n-rows x 64B, packed 2 rows/128B) ----
    uint32_t wdo[2];
    const __half* wsrc[2];
    #pragma unroll
    for (int e = 0; e < 2; e++) {
        int idx = tid * 2 + e;
        int wnr = idx >> 2, wu = idx & 3;
        wsrc[e] = g_W + (size_t)j.mat * HID * HID + (size_t)(col0 + wnr) * HID + wu * 8;
        wdo[e] = 4096u + SWZ((uint32_t)((wnr >> 1) * 128 + (wnr & 1) * 64 + wu * 16));
    }

    // ---- epilogue prefetch: row ids + wid gathers ----
    int rgs[2];
    rgs[0] = row0 + wm * 16 + (l >> 2);
    rgs[1] = rgs[0] + 8;
    int pwa[2] = {0, 0}, pwb[2] = {0, 0};
    #pragma unroll
    for (int i = 0; i < 2; i++) {
        int rg = rgs[i];
        if (mode == 1 || mode == 2 || mode == 6) {
            if (rg < R) {
                int nd = ((rg >> aL) * aRS) + aBase + (rg & aMask);
                pwa[i] = wid[nd];
            }
        } else if (mode == 3) {
            int tree = rg >> aL, jj = rg & aMask;
            pwa[i] = wid[tree * NT + ((base + jj - 1) >> 1)];
        } else if (mode == 5) {
            int tree = rg >> aL, q = rg & aMask;
            int ch = tree * NT + 2 * (aBase + q) + 1;
            pwa[i] = wid[ch];
            pwb[i] = wid[ch + 1];
        }
    }

    float acc[8][4];
    #pragma unroll
    for (int a = 0; a < 8; a++)
        #pragma unroll
        for (int q = 0; q < 4; q++) acc[a][q] = 0.f;

    float4 av[2];
#define LDA(kc) do { \
    if (!Azr) { \
        _Pragma("unroll") \
        for (int i2 = 0; i2 < 2; i2++) \
            av[i2] = Asrc ? *(const float4*)(Asrc + (kc)*32 + aq*8 + i2*4) \
                          : make_float4(0.f,0.f,0.f,0.f); \
    } else { \
        _Pragma("unroll") \
        for (int i2 = 0; i2 < 2; i2++) { \
            int off = (kc)*32 + aq*8 + i2*4; \
            float4 z = *(const float4*)(Azr + off); \
            float4 h = *(const float4*)(Ahr + off); \
            float4 s = *(const float4*)(Asrc + off); \
            av[i2].x = (1.f - z.x) * s.x + z.x * h.x; \
            av[i2].y = (1.f - z.y) * s.y + z.y * h.y; \
            av[i2].z = (1.f - z.z) * s.z + z.z * h.z; \
            av[i2].w = (1.f - z.w) * s.w + z.w * h.w; \
        } \
    } \
} while(0)
#define STSA(st, kc) do { \
    char* bp = sm + (st)*STAGE_B; \
    uint32_t pk[4]; \
    _Pragma("unroll") \
    for (int i2 = 0; i2 < 2; i2++) { \
        __half2 q0 = __floats2half2_rn(av[i2].x, av[i2].y); \
        __half2 q1 = __floats2half2_rn(av[i2].z, av[i2].w); \
        pk[2*i2]   = *(uint32_t*)&q0; \
        pk[2*i2+1] = *(uint32_t*)&q1; \
    } \
    *(uint4*)(bp + SWZ(abase)) = make_uint4(pk[0], pk[1], pk[2], pk[3]); \
    if (Om0) { \
        _Pragma("unroll") \
        for (int i2 = 0; i2 < 2; i2++) { \
            int off = (kc)*32 + aq*8 + i2*4; \
            *(float4*)(Om0 + off) = av[i2]; \
            if (Om1) *(float4*)(Om1 + off) = av[i2]; \
        } \
    } \
} while(0)
#define CPW(st, kc) do { \
    uint32_t bb = sb + (st)*STAGE_B; \
    cp16(bb + wdo[0], wsrc[0] + (kc)*32); \
    cp16(bb + wdo[1], wsrc[1] + (kc)*32); \
} while(0)

    // prologue: W chunks 0,1 in flight; A chunk 0 staged, chunk 1 in regs
    LDA(0);
    CPW(0, 0); CP_COMMIT();
    CPW(1, 1); CP_COMMIT();
    STSA(0, 0);
    LDA(1);

    const int mi = l >> 3;
    #pragma unroll 1
    for (int kc = 0; kc < 8; kc++) {
        if (kc < 7) CP_WAIT1(); else CP_WAIT0();
        __syncthreads();
        int stn = kc + 2; stn -= (stn >= 3) ? 3 : 0; stn -= (stn >= 3) ? 3 : 0;
        if (kc < 6) { CPW(stn, kc + 2); }
        CP_COMMIT();

        int st = kc; st -= (st >= 3) ? 3 : 0; st -= (st >= 3) ? 3 : 0;
        const uint32_t sA = sb + st * STAGE_B;
        #pragma unroll
        for (int ks = 0; ks < 2; ks++) {
            uint32_t fa[4];
            {
                int rrow = wm * 16 + (l & 15);
                int kb = ks * 16 + (l >> 4) * 8;
                ldsm_x4(sA + SWZ((uint32_t)((rrow >> 1) * 128 + (rrow & 1) * 64 + kb * 2)), fa);
            }
            #pragma unroll
            for (int p = 0; p < 4; p++) {
                int nrow = wn * 64 + p * 16 + (mi >> 1) * 8 + (l & 7);
                int kb2 = ks * 16 + (mi & 1) * 8;
                uint32_t bw[4];
                ldsm_x4(sA + 4096 + SWZ((uint32_t)((nrow >> 1) * 128 + (nrow & 1) * 64 + kb2 * 2)), bw);
                mma_f16(acc[2*p],   fa, &bw[0]);
                mma_f16(acc[2*p+1], fa, &bw[2]);
            }
        }
        if (kc < 7) {
            int sts = kc + 1; sts -= (sts >= 3) ? 3 : 0; sts -= (sts >= 3) ? 3 : 0;
            STSA(sts, kc + 1);
            if (kc < 6) LDA(kc + 2);
        }
    }
#undef LDA
#undef STSA
#undef CPW

    // ---------------- fused epilogues ----------------
    #pragma unroll
    for (int i = 0; i < 2; i++) {
        int rg = rgs[i];
        if (mode == 0) {
            if (rg >= R) continue;
            float* crow = j.C + (size_t)rg * HID;
            #pragma unroll
            for (int ns = 0; ns < 8; ns++) {
                int c = col0 + wn * 64 + ns * 8 + (l & 3) * 2;
                float v0 = acc[ns][i*2+0], v1 = acc[ns][i*2+1];
                if (j.bias) { v0 += j.bias[c]; v1 += j.bias[c+1]; }
                *(float2*)(crow + c) = make_float2(v0, v1);
            }
        } else if (mode == 1 || mode == 2 || mode == 6) {
            if (rg >= R) continue;
            const float* prow = j.P + (size_t)pwa[i] * HID;
            float* crow = j.C + (size_t)rg * HID;
            #pragma unroll
            for (int ns = 0; ns < 8; ns++) {
                int c = col0 + wn * 64 + ns * 8 + (l & 3) * 2;
                float v0 = acc[ns][i*2+0] + prow[c];
                float v1 = acc[ns][i*2+1] + prow[c+1];
                if      (mode == 1) { v0 = sigf(v0);       v1 = sigf(v1); }
                else if (mode == 2) { v0 = tanhf(v0);      v1 = tanhf(v1); }
                else                { v0 = fmaxf(v0, 0.f); v1 = fmaxf(v1, 0.f); }
                *(float2*)(crow + c) = make_float2(v0, v1);
            }
        } else if (mode == 3) {
            int tree = rg >> aL, jj = rg & aMask;
            int child  = tree * NT + aBase + jj;
            int parent = tree * NT + ((base + jj - 1) >> 1);
            const float* zr = j.Az + (size_t)rg * HID;
            const float* hr = j.Ah + (size_t)rg * HID;
            const float* sr = j.A  + (size_t)child * HID;
            const float* prow = j.P + (size_t)pwa[i] * HID;
            float* ds = g_s  + (size_t)parent * HID;
            float* dr = g_rm + (size_t)parent * HID;
            #pragma unroll
            for (int ns = 0; ns < 8; ns++) {
                int c = col0 + wn * 64 + ns * 8 + (l & 3) * 2;
                #pragma unroll
                for (int cc = 0; cc < 2; cc++) {
                    float z = zr[c+cc], h = hr[c+cc], s = sr[c+cc];
                    float m = (1.f - z) * s + z * h;
                    float r = sigf(acc[ns][i*2+cc] + prow[c+cc]);
                    float mr = m * r;
                    float msum  = m  + __shfl_xor_sync(0xffffffffu, m, 4);
                    float mrsum = mr + __shfl_xor_sync(0xffffffffu, mr, 4);
                    if (!(l & 4)) { ds[c+cc] = msum; dr[c+cc] = mrsum; }
                }
            }
        } else { // mode 5
            int tree = rg >> aL, q = rg & aMask;
            int pl = aBase + q;
            int parent = tree * NT + pl;
            int ch = tree * NT + 2 * pl + 1;
            const float* zr = j.Az + (size_t)rg * HID;
            const float* hr = j.Ah + (size_t)rg * HID;
            const float* sr = j.A  + (size_t)parent * HID;
            const float* p0 = j.P + (size_t)pwa[i] * HID;
            const float* p1 = j.P + (size_t)pwb[i] * HID;
            float* s0 = g_s2  + (size_t)ch * HID;
            float* r0 = g_rm2 + (size_t)ch * HID;
            #pragma unroll
            for (int ns = 0; ns < 8; ns++) {
                int c = col0 + wn * 64 + ns * 8 + (l & 3) * 2;
                #pragma unroll
                for (int cc = 0; cc < 2; cc++) {
                    float z = zr[c+cc], h = hr[c+cc], s = sr[c+cc];
                    float m = (1.f - z) * s + z * h;
                    float a = acc[ns][i*2+cc];
                    s0[c+cc]       = m;
                    s0[HID + c+cc] = m;
                    r0[c+cc]       = m * sigf(a + p0[c+cc]);
                    r0[HID + c+cc] = m * sigf(a + p1[c+cc]);
                }
            }
        }
    }
}

// ---------------- weight transpose + fp16 prep ----------------
__global__ void k_prepw(const float* __restrict__ Wz, const float* __restrict__ Wh,
                        const float* __restrict__ Wr, const float* __restrict__ Ur,
                        const float* __restrict__ Wf)
{
    const float* src;
    switch (blockIdx.x) {
        case 0: src = Wz; break;            case 1: src = Wz + 256*HID; break;
        case 2: src = Wh; break;            case 3: src = Wh + 256*HID; break;
        case 4: src = Wr; break;            case 5: src = Ur; break;
        case 6: src = Wf; break;            default: src = Wf + 256*HID; break;
    }
    int n = threadIdx.x;
    size_t mb = (size_t)blockIdx.x * HID * HID;
    int k0 = blockIdx.y * 32;
    for (int k = k0; k < k0 + 32; k++) {
        g_W[mb + (size_t)n * HID + k] = __float2half_rn(src[(size_t)k * HID + n]);
    }
}

// ---------------- structural / elementwise kernels ----------------
__global__ void k_M0() {
    size_t o = (size_t)blockIdx.x * HID + threadIdx.x;
    g_M0[o] = sigf(g_Pz[o]) * tanhf(g_Ph[o]);
}

__global__ void k_bu_leaf(const int* __restrict__ wid, float* __restrict__ out) {
    int p = blockIdx.x, jl = threadIdx.x;
    int tree = p >> 3, q = p & 7;
    int pl = 7 + q;
    int parent = tree * NT + pl;
    int c0 = 2 * pl + 1;
    int child0 = tree * NT + c0;
    int w0 = wid[child0], w1 = wid[child0 + 1];
    float pr = g_Pr[(size_t)wid[parent] * HID + jl];
    float m0 = g_M0[(size_t)w0 * HID + jl];
    float m1 = g_M0[(size_t)w1 * HID + jl];
    float r0 = sigf(pr + g_MU0[(size_t)w0 * HID + jl]);
    float r1 = sigf(pr + g_MU0[(size_t)w1 * HID + jl]);
    size_t e0 = (size_t)(tree * NE_TREE + c0 - 1) * HID + jl;
    out[e0]       = m0;
    out[e0 + HID] = m1;
    size_t po = (size_t)parent * HID + jl;
    g_s[po]  = m0 + m1;
    g_rm[po] = m0 * r0 + m1 * r1;
}

__global__ void k_td_root(const int* __restrict__ wid, float* __restrict__ out) {
    int tree = blockIdx.x, jl = threadIdx.x;
    int wr = wid[tree * NT];
    float m  = g_M0 [(size_t)wr * HID + jl];
    float mu = g_MU0[(size_t)wr * HID + jl];
    #pragma unroll
    for (int c = 1; c <= 2; c++) {
        int child = tree * NT + c;
        float r = sigf(g_Pr[(size_t)wid[child] * HID + jl] + mu);
        size_t co = (size_t)child * HID + jl;
        g_s2[co]  = m;
        g_rm2[co] = m * r;
        out[(size_t)(NE_HALF + tree * NE_TREE + c - 1) * HID + jl] = m;
    }
}

// ---------------- host ----------------
static inline void launch_g(const GJob* js, int nz,
                            int aL, int aRS, int aBase, int R,
                            const int* wid, int dlev, int base, cudaStream_t st)
{
    dim3 g((R + 63) / 64, 2, nz);
    gemm_s<<<g, 256, SM_TOT, st>>>(
        js[0], (nz>1)?js[1]:js[0], (nz>2)?js[2]:js[0], (nz>3)?js[3]:js[0],
        aL, aRS, aBase, R, wid, dlev, base);
}

extern "C" void kernel_launch(void* const* d_in, const int* in_sizes, int n_in,
                              void* d_out, int out_size)
{
    const int*   wid = (const int*)  d_in[0];
    const float* emb = (const float*)d_in[1];
    const float* Wz  = (const float*)d_in[2];
    const float* bz  = (const float*)d_in[3];
    const float* Wh  = (const float*)d_in[4];
    const float* bh  = (const float*)d_in[5];
    const float* Wr  = (const float*)d_in[6];
    const float* Ur  = (const float*)d_in[7];
    const float* bu  = (const float*)d_in[8];
    const float* Wf  = (const float*)d_in[9];
    const float* bf  = (const float*)d_in[10];
    float* out = (float*)d_out;

    float *p_s, *p_rm, *p_s2, *p_rm2, *p_Pz, *p_Ph, *p_Pr, *p_Pf, *p_M0, *p_MU0;
    float *p_T1, *p_T2, *p_T1b, *p_T2b;
    cudaGetSymbolAddress((void**)&p_s,   g_s);
    cudaGetSymbolAddress((void**)&p_rm,  g_rm);
    cudaGetSymbolAddress((void**)&p_s2,  g_s2);
    cudaGetSymbolAddress((void**)&p_rm2, g_rm2);
    cudaGetSymbolAddress((void**)&p_T1,  g_T1);
    cudaGetSymbolAddress((void**)&p_T2,  g_T2);
    cudaGetSymbolAddress((void**)&p_T1b, g_T1b);
    cudaGetSymbolAddress((void**)&p_T2b, g_T2b);
    cudaGetSymbolAddress((void**)&p_Pz,  g_Pz);
    cudaGetSymbolAddress((void**)&p_Ph,  g_Ph);
    cudaGetSymbolAddress((void**)&p_Pr,  g_Pr);
    cudaGetSymbolAddress((void**)&p_Pf,  g_Pf);
    cudaGetSymbolAddress((void**)&p_M0,  g_M0);
    cudaGetSymbolAddress((void**)&p_MU0, g_MU0);

    cudaFuncSetAttribute(gemm_s, cudaFuncAttributeMaxDynamicSharedMemorySize, SM_TOT);

    static cudaStream_t s_td = nullptr;
    static cudaEvent_t  ev_f = nullptr, ev_j = nullptr;
    if (!s_td) {
        cudaStreamCreateWithFlags(&s_td, cudaStreamNonBlocking);
        cudaEventCreateWithFlags(&ev_f, cudaEventDisableTiming);
        cudaEventCreateWithFlags(&ev_j, cudaEventDisableTiming);
    }

    // ---- prep: weights + vocab tables ----
    k_prepw<<<dim3(8, 8), 256>>>(Wz, Wh, Wr, Ur, Wf);
    {
        GJob js[4] = {
            { emb, nullptr, nullptr, p_Pz, nullptr, bz, nullptr, 0, 0 },
            { emb, nullptr, nullptr, p_Ph, nullptr, bh, nullptr, 2, 0 },
            { emb, nullptr, nullptr, p_Pr, nullptr, bu, nullptr, 4, 0 },
            { emb, nullptr, nullptr, p_Pf, nullptr, bf, nullptr, 6, 0 },
        };
        launch_g(js, 4, 0, 1, 0, VOCAB, wid, 0, 0, 0);
    }
    k_M0<<<VOCAB, HID>>>();
    {
        GJob js[1] = { { p_M0, nullptr, nullptr, p_MU0, nullptr, nullptr, nullptr, 5, 0 } };
        launch_g(js, 1, 0, 1, 0, VOCAB, wid, 0, 0, 0);
    }

    // ---- fork TD onto s_td ----
    cudaEventRecord(ev_f, 0);
    cudaStreamWaitEvent(s_td, ev_f, 0);

    // ===== bottom-up (stream 0) =====
    k_bu_leaf<<<NTREES * 8, HID>>>(wid, out);
    for (int d = 2; d >= 0; d--) {
        int L = d + 1;
        int base = (1 << (d + 1)) - 1;
        int E = NTREES << (d + 1);
        GJob zh[2] = {
            { p_s,  nullptr, nullptr, p_T1, p_Pz, nullptr, nullptr, 1, 1 },
            { p_rm, nullptr, nullptr, p_T2, p_Ph, nullptr, nullptr, 3, 2 },
        };
        launch_g(zh, 2, L, NT, base, E, wid, 0, base, 0);
        // R + fused-m + pair-reduce (writes out edge rows via y==0 loader)
        GJob jr[1] = { { p_s, p_T1, p_T2, nullptr, p_Pr, nullptr, out, 5, 3 } };
        launch_g(jr, 1, L, NT, base, E, wid, L, base, 0);
    }
    {   // h_root
        GJob jf[1] = { { p_s, nullptr, nullptr, out + (size_t)2 * NE_HALF * HID,
                         p_Pf, nullptr, nullptr, 7, 6 } };
        launch_g(jf, 1, 0, NT, 0, NTREES, wid, 0, 0, 0);
    }

    // ===== top-down (s_td) =====
    k_td_root<<<NTREES, HID, 0, s_td>>>(wid, out);
    for (int d = 1; d <= 3; d++) {
        int pb = (1 << d) - 1;
        int Pn = NTREES << d;
        GJob zh[2] = {
            { p_s2,  nullptr, nullptr, p_T1b, p_Pz, nullptr, nullptr, 1, 1 },
            { p_rm2, nullptr, nullptr, p_T2b, p_Ph, nullptr, nullptr, 3, 2 },
        };
        launch_g(zh, 2, d, NT, pb, Pn, wid, 0, pb, s_td);
        // R + fused-m + child-state writes (out rows via y==0 loader)
        GJob ju[1] = { { p_s2, p_T1b, p_T2b, nullptr, p_Pr, nullptr, out, 5, 5 } };
        launch_g(ju, 1, d, NT, pb, Pn, wid, d, 0, s_td);
    }

    // ---- join ----
    cudaEventRecord(ev_j, s_td);
    cudaStreamWaitEvent(0, ev_j, 0);
}